// round 15
// baseline (speedup 1.0000x reference)
#include <cuda_runtime.h>
#include <cuda_fp16.h>
#include <math.h>
#include <stdint.h>

#define S_   256
#define B_   512
#define H_   512
#define E_   256
#define L_   4
#define OUT_ 128

// ---------------- scratch (no allocs allowed) ----------------
__device__ float  g_Wh[B_ * H_];
__device__ float  g_energyT[B_ * S_];     // transposed: [b][s]
__device__ __half g_UwH[H_ * H_];
__device__ __half g_WiH0[3 * H_ * (H_ + E_)];
__device__ __half g_WhH0[3 * H_ * H_];
__device__ __half g_WiHr[(L_ - 1) * 3 * H_ * H_];
__device__ __half g_WhHr[(L_ - 1) * 3 * H_ * H_];
__device__ __half g_hidH[L_ * B_ * H_];
__device__ __half g_rnnH[B_ * (H_ + E_)];
__device__ __half g_houtH[L_ * B_ * H_];
__device__ int    g_bar[L_];              // grid barrier counters (reset by cvt_all)

// ---------------- helpers ----------------
__device__ __forceinline__ uint32_t smem_u32(const void* p) {
    uint32_t a;
    asm("{ .reg .u64 t; cvta.to.shared.u64 t, %1; cvt.u32.u64 %0, t; }" : "=r"(a) : "l"(p));
    return a;
}
__device__ __forceinline__ void ldsm4(uint32_t* r, uint32_t addr) {
    asm volatile("ldmatrix.sync.aligned.m8n8.x4.shared.b16 {%0,%1,%2,%3}, [%4];"
                 : "=r"(r[0]), "=r"(r[1]), "=r"(r[2]), "=r"(r[3]) : "r"(addr));
}
__device__ __forceinline__ void mma16816(float* c, const uint32_t* a, uint32_t b0, uint32_t b1) {
    asm volatile(
        "mma.sync.aligned.m16n8k16.row.col.f32.f16.f16.f32 "
        "{%0,%1,%2,%3}, {%4,%5,%6,%7}, {%8,%9}, {%0,%1,%2,%3};\n"
        : "+f"(c[0]), "+f"(c[1]), "+f"(c[2]), "+f"(c[3])
        : "r"(a[0]), "r"(a[1]), "r"(a[2]), "r"(a[3]), "r"(b0), "r"(b1));
}
__device__ __forceinline__ void cp16(uint32_t daddr, const void* saddr) {
    asm volatile("cp.async.cg.shared.global [%0], [%1], 16;" :: "r"(daddr), "l"(saddr) : "memory");
}
#define CP_COMMIT() asm volatile("cp.async.commit_group;" ::: "memory")
#define CP_WAIT(n)  asm volatile("cp.async.wait_group " #n ";" ::: "memory")

__device__ __forceinline__ void sts16(__half* dst, float4 v) {
    __half2* d = (__half2*)dst;
    d[0] = __float22half2_rn(make_float2(v.x, v.y));
    d[1] = __float22half2_rn(make_float2(v.z, v.w));
}
__device__ __forceinline__ uint32_t packh2(float a, float b) {
    __half2 h = __float22half2_rn(make_float2(a, b));
    return *reinterpret_cast<uint32_t*>(&h);
}
__device__ __forceinline__ float ftanh(float x) {
    float e = __expf(2.f * x);
    return 1.f - __fdividef(2.f, e + 1.f);
}
__device__ __forceinline__ float fsig(float x) {
    return __fdividef(1.f, 1.f + __expf(-x));
}

// ---------------- merged fp32 -> fp16 conversions + barrier reset ----------------
#define Q_UW   (H_ * H_ / 4)
#define Q_WI0  (Q_UW + 3 * H_ * (H_ + E_) / 4)
#define Q_WH0  (Q_WI0 + 3 * H_ * H_ / 4)
#define Q_WIR  (Q_WH0 + (L_ - 1) * 3 * H_ * H_ / 4)
#define Q_WHR  (Q_WIR + (L_ - 1) * 3 * H_ * H_ / 4)
#define Q_HID  (Q_WHR + L_ * B_ * H_ / 4)
#define CVT_BLOCKS (Q_HID / 256)

__global__ void cvt_all_kernel(
    const float* __restrict__ Uw,   __half* __restrict__ UwH,
    const float* __restrict__ wi0,  __half* __restrict__ WiH0,
    const float* __restrict__ wh0,  __half* __restrict__ WhH0,
    const float* __restrict__ wir,  __half* __restrict__ WiHr,
    const float* __restrict__ whr,  __half* __restrict__ WhHr,
    const float* __restrict__ hid,  __half* __restrict__ hidH) {
    const int i = blockIdx.x * 256 + threadIdx.x;
    if (blockIdx.x == 0 && threadIdx.x < L_) g_bar[threadIdx.x] = 0;
    const float* src;
    __half* dst;
    int off;
    if (i < Q_UW)       { src = Uw;  dst = UwH;  off = 0; }
    else if (i < Q_WI0) { src = wi0; dst = WiH0; off = Q_UW; }
    else if (i < Q_WH0) { src = wh0; dst = WhH0; off = Q_WI0; }
    else if (i < Q_WIR) { src = wir; dst = WiHr; off = Q_WH0; }
    else if (i < Q_WHR) { src = whr; dst = WhHr; off = Q_WIR; }
    else                { src = hid; dst = hidH; off = Q_WHR; }
    const int j = i - off;
    float4 v = ((const float4*)src)[j];
    uint2 o;
    o.x = packh2(v.x, v.y);
    o.y = packh2(v.z, v.w);
    ((uint2*)dst)[j] = o;
}

// ============================================================
// Energy kernel: 32-k iterations, 3-stage cp.async (unchanged R14).
// ============================================================
#define EASZ 20480
#define EWSZ 20480
#define ESTG (EASZ + EWSZ)
#define ESMEM_DYN (512 + 3 * ESTG)

__global__ void __launch_bounds__(512, 1) energy_async_kernel(
    const float* __restrict__ Es, const __half* __restrict__ UwH,
    const float* __restrict__ Ub, const float* __restrict__ Wh,
    const float* __restrict__ aw, const float* __restrict__ ab,
    float* __restrict__ energyT) {
    extern __shared__ __align__(16) char dsm[];
    float* esum = (float*)dsm;
    char* tiles = dsm + 512;
    const uint32_t tBase = smem_u32(tiles);

    const int tid = threadIdx.x;
    const int lane = tid & 31, wid = tid >> 5;
    const int wm = wid >> 3, wn = wid & 7;
    const int g = lane >> 2, tg = lane & 3;
    const int lr = (lane & 7) + ((lane >> 3) & 1) * 8;
    const int lb = ((lane >> 4) & 1) * 16;
    const int r0 = blockIdx.x * 128;
    const int b0 = r0 & (B_ - 1);

    const int aRow0 = tid >> 3, aQ0 = tid & 7;
    const int aRow1 = (tid + 512) >> 3, aQ1 = (tid + 512) & 7;
    const int wRow0 = tid >> 2, wQ0 = tid & 3;
    const int wRow1 = (tid + 512) >> 2, wQ1 = (tid + 512) & 3;

    if (tid < 128) esum[tid] = 0.f;
    __syncthreads();

    for (int nc = 0; nc < 2; nc++) {
        const float* Abase = Es + (size_t)r0 * H_;
        const __half* Wb2 = UwH + (size_t)(nc * 256) * H_;
        float acc[4][4][4] = {};

#pragma unroll
        for (int s = 0; s < 2; s++) {
            const uint32_t sb = tBase + (uint32_t)s * ESTG;
            cp16(sb + aRow0 * 160 + aQ0 * 16, Abase + (size_t)aRow0 * H_ + s * 32 + aQ0 * 4);
            cp16(sb + aRow1 * 160 + aQ1 * 16, Abase + (size_t)aRow1 * H_ + s * 32 + aQ1 * 4);
            cp16(sb + EASZ + wRow0 * 80 + wQ0 * 16, Wb2 + (size_t)wRow0 * H_ + s * 32 + wQ0 * 8);
            cp16(sb + EASZ + wRow1 * 80 + wQ1 * 16, Wb2 + (size_t)wRow1 * H_ + s * 32 + wQ1 * 8);
            CP_COMMIT();
        }

        for (int it = 0; it < 16; it++) {
            const int s = it % 3;
            CP_WAIT(1);
            __syncthreads();

            const float* sA = (const float*)(tiles + s * ESTG);
            const uint32_t wOff = tBase + (uint32_t)s * ESTG + EASZ;

#pragma unroll
            for (int ks = 0; ks < 2; ks++) {
                uint32_t af[4][4];
#pragma unroll
                for (int mi = 0; mi < 4; mi++) {
                    const int rb = wm * 64 + mi * 16 + g;
                    const int cb = ks * 16 + tg * 2;
                    float2 f0 = *(const float2*)&sA[rb * 40 + cb];
                    float2 f1 = *(const float2*)&sA[(rb + 8) * 40 + cb];
                    float2 f2 = *(const float2*)&sA[rb * 40 + cb + 8];
                    float2 f3 = *(const float2*)&sA[(rb + 8) * 40 + cb + 8];
                    af[mi][0] = packh2(f0.x, f0.y);
                    af[mi][1] = packh2(f1.x, f1.y);
                    af[mi][2] = packh2(f2.x, f2.y);
                    af[mi][3] = packh2(f3.x, f3.y);
                }
                uint32_t bt[2][4];
#pragma unroll
                for (int nt = 0; nt < 2; nt++)
                    ldsm4(bt[nt], wOff + (uint32_t)(wn * 32 + nt * 16 + lr) * 80 + ks * 32 + lb);
#pragma unroll
                for (int mi = 0; mi < 4; mi++)
#pragma unroll
                    for (int ni = 0; ni < 4; ni++) {
                        const int nt = ni >> 1, sub = ni & 1;
                        mma16816(acc[mi][ni], af[mi], bt[nt][sub ? 1 : 0], bt[nt][sub ? 3 : 2]);
                    }
            }
            if (it + 2 < 16) {
                const int ns = (it + 2) % 3;
                const uint32_t sb = tBase + (uint32_t)ns * ESTG;
                cp16(sb + aRow0 * 160 + aQ0 * 16, Abase + (size_t)aRow0 * H_ + (it + 2) * 32 + aQ0 * 4);
                cp16(sb + aRow1 * 160 + aQ1 * 16, Abase + (size_t)aRow1 * H_ + (it + 2) * 32 + aQ1 * 4);
                cp16(sb + EASZ + wRow0 * 80 + wQ0 * 16, Wb2 + (size_t)wRow0 * H_ + (it + 2) * 32 + wQ0 * 8);
                cp16(sb + EASZ + wRow1 * 80 + wQ1 * 16, Wb2 + (size_t)wRow1 * H_ + (it + 2) * 32 + wQ1 * 8);
            }
            CP_COMMIT();
        }

#pragma unroll
        for (int mi = 0; mi < 4; mi++)
#pragma unroll
            for (int hf = 0; hf < 2; hf++) {
                const int rl = wm * 64 + mi * 16 + g + hf * 8;
                const float* WhR = Wh + (size_t)(b0 + rl) * H_;
                float s = 0.f;
#pragma unroll
                for (int ni = 0; ni < 4; ni++) {
                    const int col = nc * 256 + wn * 32 + ni * 8 + tg * 2;
                    float v0 = acc[mi][ni][hf * 2 + 0] + Ub[col] + WhR[col];
                    float v1 = acc[mi][ni][hf * 2 + 1] + Ub[col + 1] + WhR[col + 1];
                    s += ftanh(v0) * aw[col] + ftanh(v1) * aw[col + 1];
                }
                s += __shfl_xor_sync(0xffffffffu, s, 1);
                s += __shfl_xor_sync(0xffffffffu, s, 2);
                if (tg == 0) atomicAdd(&esum[rl], s);
            }
        __syncthreads();
    }
    if (tid < 128) {
        const int r = r0 + tid;
        energyT[(size_t)(r & (B_ - 1)) * S_ + (r >> 9)] = esum[tid] + ab[0];
    }
}

// ============================================================
// ALL 4 GRU layers in one kernel, software grid barriers.
// Grid = (16, 8) = 128 CTAs <= 148 SMs -> all co-resident.
// Per layer: same 32-k / 3-stage cp.async pipeline as R14.
// ============================================================
#define GSTG (320 * 80)
#define GSMEM_DYN (3 * GSTG)

__global__ void __launch_bounds__(256, 1) gru_all_kernel(
    const __half* __restrict__ rnnH,
    const __half* __restrict__ WiH0, const __half* __restrict__ WhH0,
    const __half* __restrict__ WiHr, const __half* __restrict__ WhHr,
    const __half* __restrict__ hidH, const float* __restrict__ hidden,
    const float* __restrict__ b_ih0, const float* __restrict__ b_hh0,
    const float* __restrict__ b_ih_r, const float* __restrict__ b_hh_r,
    float* __restrict__ hid_out, __half* __restrict__ houtH) {
    extern __shared__ __align__(16) char sm[];

    const int tid = threadIdx.x;
    const int lane = tid & 31, wid = tid >> 5;
    const int wm = wid >> 1, wn = wid & 1;
    const int gl = lane >> 2, tg = lane & 3;
    const int lr = (lane & 7) + ((lane >> 3) & 1) * 8;
    const int lb = ((lane >> 4) & 1) * 16;
    const int m0 = blockIdx.y * 64;
    const int nb = blockIdx.x * 32;
    const uint32_t base = smem_u32(sm);

    for (int l = 0; l < L_; l++) {
        const int KI = (l == 0) ? (H_ + E_) : H_;
        const int NIT = KI / 32;
        const __half* AiH = (l == 0) ? rnnH : houtH + (size_t)(l - 1) * B_ * H_;
        const __half* WiH = (l == 0) ? WiH0 : WiHr + (size_t)(l - 1) * 3 * H_ * H_;
        const __half* WhH = (l == 0) ? WhH0 : WhHr + (size_t)(l - 1) * 3 * H_ * H_;
        const __half* AhH = hidH + (size_t)l * B_ * H_;
        const float*  Ahf = hidden + (size_t)l * B_ * H_;
        const float*  bi  = (l == 0) ? b_ih0 : b_ih_r + (size_t)(l - 1) * 3 * H_;
        const float*  bh  = (l == 0) ? b_hh0 : b_hh_r + (size_t)(l - 1) * 3 * H_;
        float* hout  = hid_out + (size_t)l * B_ * H_;
        __half* hoH  = houtH + (size_t)l * B_ * H_;

        // fill descriptors: 1280 cp16 (320 rows x 4 quads), 5 per thread
        const __half* srcp[5];
        uint32_t dsto[5];
        bool ish[5];
#pragma unroll
        for (int i = 0; i < 5; i++) {
            const int idx = i * 256 + tid;
            const int row = idx >> 2, quad = idx & 3;
            const __half* p;
            bool h;
            if (row < 64)       { p = AiH + (size_t)(m0 + row) * KI; h = false; }
            else if (row < 128) { p = AhH + (size_t)(m0 + row - 64) * H_; h = true; }
            else if (row < 224) { const int q = row - 128; p = WiH + (size_t)((q >> 5) * H_ + nb + (q & 31)) * KI; h = false; }
            else                { const int q = row - 224; p = WhH + (size_t)((q >> 5) * H_ + nb + (q & 31)) * H_; h = true; }
            srcp[i] = p + quad * 8;
            dsto[i] = row * 80 + quad * 16;
            ish[i] = h;
        }

        float acc_rz[2][2][4] = {};
        float acc_n0[2][4] = {};
        float acc_n1[2][4] = {};
        const int NHIT = H_ / 32;   // 16

        // prologue stages 0,1 (s < NHIT always)
#pragma unroll
        for (int s = 0; s < 2; s++) {
#pragma unroll
            for (int i = 0; i < 5; i++)
                cp16(base + s * GSTG + dsto[i], srcp[i] + s * 32);
            CP_COMMIT();
        }

        for (int it = 0; it < NIT; it++) {
            const int s = it % 3;
            CP_WAIT(1);
            __syncthreads();

            const uint32_t off = base + (uint32_t)s * GSTG;
            const bool act_h = (it < NHIT);
#pragma unroll
            for (int ks = 0; ks < 2; ks++) {
                const uint32_t lbk = (uint32_t)(ks * 32 + lb);
                uint32_t afi[4], afh[4], bwi[3][4], bwh[3][4];
                ldsm4(afi, off + (uint32_t)(wm * 16 + lr) * 80 + lbk);
#pragma unroll
                for (int gt = 0; gt < 3; gt++)
                    ldsm4(bwi[gt], off + (uint32_t)(128 + gt * 32 + wn * 16 + lr) * 80 + lbk);
                if (act_h) {
                    ldsm4(afh, off + (uint32_t)(64 + wm * 16 + lr) * 80 + lbk);
#pragma unroll
                    for (int gt = 0; gt < 3; gt++)
                        ldsm4(bwh[gt], off + (uint32_t)(224 + gt * 32 + wn * 16 + lr) * 80 + lbk);
                }
#pragma unroll
                for (int sub = 0; sub < 2; sub++) {
                    mma16816(acc_rz[0][sub], afi, bwi[0][sub], bwi[0][sub + 2]);
                    mma16816(acc_rz[1][sub], afi, bwi[1][sub], bwi[1][sub + 2]);
                    mma16816(acc_n0[sub],    afi, bwi[2][sub], bwi[2][sub + 2]);
                }
                if (act_h) {
#pragma unroll
                    for (int sub = 0; sub < 2; sub++) {
                        mma16816(acc_rz[0][sub], afh, bwh[0][sub], bwh[0][sub + 2]);
                        mma16816(acc_rz[1][sub], afh, bwh[1][sub], bwh[1][sub + 2]);
                        mma16816(acc_n1[sub],    afh, bwh[2][sub], bwh[2][sub + 2]);
                    }
                }
            }
            if (it + 2 < NIT) {
                const int ns = (it + 2) % 3;
#pragma unroll
                for (int i = 0; i < 5; i++)
                    if (!ish[i] || (it + 2) < NHIT)
                        cp16(base + ns * GSTG + dsto[i], srcp[i] + (it + 2) * 32);
            }
            CP_COMMIT();
        }

        // epilogue: gate nonlinearity, h update
#pragma unroll
        for (int hf = 0; hf < 2; hf++) {
            const int row = m0 + wm * 16 + gl + hf * 8;
#pragma unroll
            for (int sub = 0; sub < 2; sub++) {
                const int col = nb + wn * 16 + sub * 8 + tg * 2;
                float2 hp = *(const float2*)&Ahf[(size_t)row * H_ + col];
                float2 o;
#pragma unroll
                for (int j = 0; j < 2; j++) {
                    const int cj = col + j;
                    float rr = fsig(acc_rz[0][sub][hf * 2 + j] + bi[cj] + bh[cj]);
                    float zz = fsig(acc_rz[1][sub][hf * 2 + j] + bi[H_ + cj] + bh[H_ + cj]);
                    float nn = ftanh(acc_n0[sub][hf * 2 + j] + bi[2 * H_ + cj] +
                                     rr * (acc_n1[sub][hf * 2 + j] + bh[2 * H_ + cj]));
                    float hv = j ? hp.y : hp.x;
                    float res = fmaf(zz, hv - nn, nn);
                    if (j) o.y = res; else o.x = res;
                }
                *(float2*)&hout[(size_t)row * H_ + col] = o;
                *(__half2*)&hoH[(size_t)row * H_ + col] = __float22half2_rn(o);
            }
        }

        // grid barrier before next layer reads houtH
        if (l + 1 < L_) {
            __threadfence();
            __syncthreads();
            if (tid == 0) {
                atomicAdd(&g_bar[l], 1);
                while (atomicAdd(&g_bar[l], 0) < 128) {}
            }
            __syncthreads();
        }
    }
}

// ---------------- small GEMM: C[M,N] = A@W^T + bias (fp32 in, 64x64) ----------------
__global__ void __launch_bounds__(256, 2) sgemm64_kernel(
    const float* __restrict__ A, const float* __restrict__ W,
    const float* __restrict__ bias, float* __restrict__ C, int K, int N) {
    __shared__ __align__(16) __half sm[2 * 128 * 24];

    const int tid = threadIdx.x;
    const int lane = tid & 31, wid = tid >> 5;
    const int wm = wid >> 1, wn = wid & 1;
    const int g = lane >> 2, tg = lane & 3;
    const int lr = (lane & 7) + ((lane >> 3) & 1) * 8;
    const int lb = ((lane >> 4) & 1) * 16;
    const int m0 = blockIdx.y * 64, n0 = blockIdx.x * 64;
    const uint32_t base = smem_u32(sm);

    const int r = tid >> 2, c = (tid & 3) * 4;
    float acc[4][4] = {};
    float4 ra, rw;
    ra = *(const float4*)&A[(size_t)(m0 + r) * K + c];
    rw = *(const float4*)&W[(size_t)(n0 + r) * K + c];
    sts16(sm + r * 24 + c, ra);
    sts16(sm + (64 + r) * 24 + c, rw);
    __syncthreads();

    const int nk = K / 16;
    for (int kt = 0; kt < nk; kt++) {
        const int p = kt & 1;
        if (kt + 1 < nk) {
            ra = *(const float4*)&A[(size_t)(m0 + r) * K + (kt + 1) * 16 + c];
            rw = *(const float4*)&W[(size_t)(n0 + r) * K + (kt + 1) * 16 + c];
        }
        const uint32_t off = base + (uint32_t)p * 128 * 48;
        uint32_t af[4], bt[2][4];
        ldsm4(af, off + (uint32_t)(wm * 16 + lr) * 48 + lb);
#pragma unroll
        for (int nt = 0; nt < 2; nt++)
            ldsm4(bt[nt], off + (uint32_t)(64 + wn * 32 + nt * 16 + lr) * 48 + lb);
#pragma unroll
        for (int ni = 0; ni < 4; ni++) {
            const int nt = ni >> 1, sub = ni & 1;
            mma16816(acc[ni], af, bt[nt][sub ? 1 : 0], bt[nt][sub ? 3 : 2]);
        }
        if (kt + 1 < nk) {
            __half* d = sm + (p ^ 1) * 128 * 24;
            sts16(d + r * 24 + c, ra);
            sts16(d + (64 + r) * 24 + c, rw);
        }
        __syncthreads();
    }

#pragma unroll
    for (int hf = 0; hf < 2; hf++) {
        const int row = m0 + wm * 16 + g + hf * 8;
#pragma unroll
        for (int ni = 0; ni < 4; ni++) {
            const int col = n0 + wn * 32 + ni * 8 + tg * 2;
            float2 o;
            o.x = acc[ni][hf * 2 + 0] + bias[col];
            o.y = acc[ni][hf * 2 + 1] + bias[col + 1];
            *(float2*)&C[(size_t)row * N + col] = o;
        }
    }
}

// ============================================================
// attn+context+emb: grid (4, B), 128 threads, 8-way MLP.
// ============================================================
__global__ void __launch_bounds__(128) attn_ctx_kernel(
    const float* __restrict__ energyT, const float* __restrict__ Es,
    const int* __restrict__ x, const float* __restrict__ emb,
    __half* __restrict__ rnnH) {
    __shared__ float sv[S_];
    __shared__ float att[S_];
    const int q = blockIdx.x;
    const int b = blockIdx.y;
    const int t = threadIdx.x;

    float e0 = energyT[(size_t)b * S_ + t];
    float e1 = energyT[(size_t)b * S_ + 128 + t];
    sv[t] = fmaxf(e0, e1);
    __syncthreads();
    for (int off = 64; off; off >>= 1) {
        if (t < off) sv[t] = fmaxf(sv[t], sv[t + off]);
        __syncthreads();
    }
    const float m = sv[0];
    __syncthreads();
    float x0 = __expf(e0 - m), x1 = __expf(e1 - m);
    att[t] = x0;
    att[t + 128] = x1;
    sv[t] = x0 + x1;
    __syncthreads();
    for (int off = 64; off; off >>= 1) {
        if (t < off) sv[t] += sv[t + off];
        __syncthreads();
    }
    const float inv = __fdividef(1.f, sv[0]);
    __syncthreads();

    // context: h = q*128 + t, 8 independent accumulators
    const int h = q * 128 + t;
    const float* base = Es + (size_t)b * H_ + h;
    float a0 = 0.f, a1 = 0.f, a2 = 0.f, a3 = 0.f;
    float a4 = 0.f, a5 = 0.f, a6 = 0.f, a7 = 0.f;
    for (int s = 0; s < S_; s += 8) {
        a0 = fmaf(att[s + 0], base[(size_t)(s + 0) * B_ * H_], a0);
        a1 = fmaf(att[s + 1], base[(size_t)(s + 1) * B_ * H_], a1);
        a2 = fmaf(att[s + 2], base[(size_t)(s + 2) * B_ * H_], a2);
        a3 = fmaf(att[s + 3], base[(size_t)(s + 3) * B_ * H_], a3);
        a4 = fmaf(att[s + 4], base[(size_t)(s + 4) * B_ * H_], a4);
        a5 = fmaf(att[s + 5], base[(size_t)(s + 5) * B_ * H_], a5);
        a6 = fmaf(att[s + 6], base[(size_t)(s + 6) * B_ * H_], a6);
        a7 = fmaf(att[s + 7], base[(size_t)(s + 7) * B_ * H_], a7);
    }
    float ctx = ((a0 + a1) + (a2 + a3)) + ((a4 + a5) + (a6 + a7));
    rnnH[(size_t)b * (H_ + E_) + h] = __float2half(ctx * inv);

    // embedding: 4 blocks x 64 lanes cover E_=256
    if (t < 64) {
        const int col = q * 64 + t;
        rnnH[(size_t)b * (H_ + E_) + H_ + col] = __float2half(emb[(size_t)x[b] * E_ + col]);
    }
}

// ---------------- launch ----------------
extern "C" void kernel_launch(void* const* d_in, const int* in_sizes, int n_in,
                              void* d_out, int out_size) {
    const int*   x      = (const int*)  d_in[0];
    const float* Es     = (const float*)d_in[1];
    const float* hidden = (const float*)d_in[2];
    const float* emb    = (const float*)d_in[4];
    const float* Uw     = (const float*)d_in[5];
    const float* Ub     = (const float*)d_in[6];
    const float* Ww     = (const float*)d_in[7];
    const float* Wb     = (const float*)d_in[8];
    const float* aw     = (const float*)d_in[9];
    const float* ab     = (const float*)d_in[10];
    const float* w_ih0  = (const float*)d_in[11];
    const float* w_hh0  = (const float*)d_in[12];
    const float* b_ih0  = (const float*)d_in[13];
    const float* b_hh0  = (const float*)d_in[14];
    const float* w_ih_r = (const float*)d_in[15];
    const float* w_hh_r = (const float*)d_in[16];
    const float* b_ih_r = (const float*)d_in[17];
    const float* b_hh_r = (const float*)d_in[18];
    const float* fcw    = (const float*)d_in[19];
    const float* fcb    = (const float*)d_in[20];

    float* out     = (float*)d_out;
    float* pred    = out;               // [B, OUT]
    float* hid_out = out + B_ * OUT_;   // [L, B, H]

    float *Wh, *energyT;
    __half *UwH, *WiH0, *WhH0, *WiHr, *WhHr, *hidH, *rnnH, *houtH;
    cudaGetSymbolAddress((void**)&Wh,      g_Wh);
    cudaGetSymbolAddress((void**)&energyT, g_energyT);
    cudaGetSymbolAddress((void**)&UwH,     g_UwH);
    cudaGetSymbolAddress((void**)&WiH0,    g_WiH0);
    cudaGetSymbolAddress((void**)&WhH0,    g_WhH0);
    cudaGetSymbolAddress((void**)&WiHr,    g_WiHr);
    cudaGetSymbolAddress((void**)&WhHr,    g_WhHr);
    cudaGetSymbolAddress((void**)&hidH,    g_hidH);
    cudaGetSymbolAddress((void**)&rnnH,    g_rnnH);
    cudaGetSymbolAddress((void**)&houtH,   g_houtH);

    cudaFuncSetAttribute(energy_async_kernel,
                         cudaFuncAttributeMaxDynamicSharedMemorySize, ESMEM_DYN);
    cudaFuncSetAttribute(gru_all_kernel,
                         cudaFuncAttributeMaxDynamicSharedMemorySize, GSMEM_DYN);

    const float* hlast = hidden + (size_t)(L_ - 1) * B_ * H_;

    // 0) conversions + barrier reset (one launch)
    cvt_all_kernel<<<CVT_BLOCKS, 256>>>(Uw, UwH, w_ih0, WiH0, w_hh0, WhH0,
                                        w_ih_r, WiHr, w_hh_r, WhHr, hidden, hidH);

    // 1) Wh = hidden[-1] @ Ww^T + Wb
    sgemm64_kernel<<<dim3(H_ / 64, B_ / 64), 256>>>(hlast, Ww, Wb, Wh, H_, H_);

    // 2) fused energy -> energyT[b][s]
    energy_async_kernel<<<(S_ * B_) / 128, 512, ESMEM_DYN>>>(
        Es, UwH, Ub, Wh, aw, ab, energyT);

    // 3) softmax + context + embedding -> fp16 rnn
    attn_ctx_kernel<<<dim3(4, B_), 128>>>(energyT, Es, x, emb, rnnH);

    // 4) ALL GRU layers in one launch (software grid barriers)
    gru_all_kernel<<<dim3(H_ / 32, B_ / 64), 256, GSMEM_DYN>>>(
        rnnH, WiH0, WhH0, WiHr, WhHr, hidH, hidden,
        b_ih0, b_hh0, b_ih_r, b_hh_r, hid_out, houtH);

    // 5) predictions = h_last @ fcw^T + fcb
    sgemm64_kernel<<<dim3(OUT_ / 64, B_ / 64), 256>>>(
        hid_out + (size_t)(L_ - 1) * B_ * H_, fcw, fcb, pred, H_, OUT_);
}

// round 16
// speedup vs baseline: 1.0239x; 1.0239x over previous
#include <cuda_runtime.h>
#include <cuda_fp16.h>
#include <math.h>
#include <stdint.h>

#define S_   256
#define B_   512
#define H_   512
#define E_   256
#define L_   4
#define OUT_ 128

// ---------------- scratch (no allocs allowed) ----------------
__device__ float  g_Wh[B_ * H_];
__device__ float  g_energyT[B_ * S_];     // transposed: [b][s]
__device__ __half g_UwH[H_ * H_];
__device__ __half g_WiH0[3 * H_ * (H_ + E_)];
__device__ __half g_WhH0[3 * H_ * H_];
__device__ __half g_WiHr[(L_ - 1) * 3 * H_ * H_];
__device__ __half g_WhHr[(L_ - 1) * 3 * H_ * H_];
__device__ __half g_hidH[L_ * B_ * H_];
__device__ __half g_rnnH[B_ * (H_ + E_)];
__device__ __half g_houtH[L_ * B_ * H_];

// ---------------- helpers ----------------
__device__ __forceinline__ uint32_t smem_u32(const void* p) {
    uint32_t a;
    asm("{ .reg .u64 t; cvta.to.shared.u64 t, %1; cvt.u32.u64 %0, t; }" : "=r"(a) : "l"(p));
    return a;
}
__device__ __forceinline__ void ldsm4(uint32_t* r, uint32_t addr) {
    asm volatile("ldmatrix.sync.aligned.m8n8.x4.shared.b16 {%0,%1,%2,%3}, [%4];"
                 : "=r"(r[0]), "=r"(r[1]), "=r"(r[2]), "=r"(r[3]) : "r"(addr));
}
__device__ __forceinline__ void mma16816(float* c, const uint32_t* a, uint32_t b0, uint32_t b1) {
    asm volatile(
        "mma.sync.aligned.m16n8k16.row.col.f32.f16.f16.f32 "
        "{%0,%1,%2,%3}, {%4,%5,%6,%7}, {%8,%9}, {%0,%1,%2,%3};\n"
        : "+f"(c[0]), "+f"(c[1]), "+f"(c[2]), "+f"(c[3])
        : "r"(a[0]), "r"(a[1]), "r"(a[2]), "r"(a[3]), "r"(b0), "r"(b1));
}
__device__ __forceinline__ void cp16(uint32_t daddr, const void* saddr) {
    asm volatile("cp.async.cg.shared.global [%0], [%1], 16;" :: "r"(daddr), "l"(saddr) : "memory");
}
#define CP_COMMIT() asm volatile("cp.async.commit_group;" ::: "memory")
#define CP_WAIT(n)  asm volatile("cp.async.wait_group " #n ";" ::: "memory")

__device__ __forceinline__ void sts16(__half* dst, float4 v) {
    __half2* d = (__half2*)dst;
    d[0] = __float22half2_rn(make_float2(v.x, v.y));
    d[1] = __float22half2_rn(make_float2(v.z, v.w));
}
__device__ __forceinline__ uint32_t packh2(float a, float b) {
    __half2 h = __float22half2_rn(make_float2(a, b));
    return *reinterpret_cast<uint32_t*>(&h);
}
__device__ __forceinline__ float ftanh(float x) {
    float e = __expf(2.f * x);
    return 1.f - __fdividef(2.f, e + 1.f);
}
__device__ __forceinline__ float fsig(float x) {
    return __fdividef(1.f, 1.f + __expf(-x));
}

// ---------------- merged fp32 -> fp16 conversions (one launch) ----------------
#define Q_UW   (H_ * H_ / 4)
#define Q_WI0  (Q_UW + 3 * H_ * (H_ + E_) / 4)
#define Q_WH0  (Q_WI0 + 3 * H_ * H_ / 4)
#define Q_WIR  (Q_WH0 + (L_ - 1) * 3 * H_ * H_ / 4)
#define Q_WHR  (Q_WIR + (L_ - 1) * 3 * H_ * H_ / 4)
#define Q_HID  (Q_WHR + L_ * B_ * H_ / 4)
#define CVT_BLOCKS (Q_HID / 256)

__global__ void cvt_all_kernel(
    const float* __restrict__ Uw,   __half* __restrict__ UwH,
    const float* __restrict__ wi0,  __half* __restrict__ WiH0,
    const float* __restrict__ wh0,  __half* __restrict__ WhH0,
    const float* __restrict__ wir,  __half* __restrict__ WiHr,
    const float* __restrict__ whr,  __half* __restrict__ WhHr,
    const float* __restrict__ hid,  __half* __restrict__ hidH) {
    const int i = blockIdx.x * 256 + threadIdx.x;
    const float* src;
    __half* dst;
    int off;
    if (i < Q_UW)       { src = Uw;  dst = UwH;  off = 0; }
    else if (i < Q_WI0) { src = wi0; dst = WiH0; off = Q_UW; }
    else if (i < Q_WH0) { src = wh0; dst = WhH0; off = Q_WI0; }
    else if (i < Q_WIR) { src = wir; dst = WiHr; off = Q_WH0; }
    else if (i < Q_WHR) { src = whr; dst = WhHr; off = Q_WIR; }
    else                { src = hid; dst = hidH; off = Q_WHR; }
    const int j = i - off;
    float4 v = ((const float4*)src)[j];
    uint2 o;
    o.x = packh2(v.x, v.y);
    o.y = packh2(v.z, v.w);
    ((uint2*)dst)[j] = o;
}

// ============================================================
// Energy kernel: 32-k iterations, 4-stage cp.async pipeline
// (prefetch distance 3, CP_WAIT(2)). smem 164KB, 1 CTA/SM.
// ============================================================
#define EASZ 20480                  // A: 128 rows * 160B
#define EWSZ 20480                  // W: 256 rows * 80B
#define ESTG (EASZ + EWSZ)
#define ESMEM_DYN (512 + 4 * ESTG)  // 164352

__global__ void __launch_bounds__(512, 1) energy_async_kernel(
    const float* __restrict__ Es, const __half* __restrict__ UwH,
    const float* __restrict__ Ub, const float* __restrict__ Wh,
    const float* __restrict__ aw, const float* __restrict__ ab,
    float* __restrict__ energyT) {
    extern __shared__ __align__(16) char dsm[];
    float* esum = (float*)dsm;
    char* tiles = dsm + 512;
    const uint32_t tBase = smem_u32(tiles);

    const int tid = threadIdx.x;
    const int lane = tid & 31, wid = tid >> 5;
    const int wm = wid >> 3, wn = wid & 7;
    const int g = lane >> 2, tg = lane & 3;
    const int lr = (lane & 7) + ((lane >> 3) & 1) * 8;
    const int lb = ((lane >> 4) & 1) * 16;
    const int r0 = blockIdx.x * 128;
    const int b0 = r0 & (B_ - 1);

    const int aRow0 = tid >> 3, aQ0 = tid & 7;
    const int aRow1 = (tid + 512) >> 3, aQ1 = (tid + 512) & 7;
    const int wRow0 = tid >> 2, wQ0 = tid & 3;
    const int wRow1 = (tid + 512) >> 2, wQ1 = (tid + 512) & 3;

    if (tid < 128) esum[tid] = 0.f;
    __syncthreads();

    for (int nc = 0; nc < 2; nc++) {
        const float* Abase = Es + (size_t)r0 * H_;
        const __half* Wb2 = UwH + (size_t)(nc * 256) * H_;
        float acc[4][4][4] = {};

        // prologue: stages 0..2
#pragma unroll
        for (int s = 0; s < 3; s++) {
            const uint32_t sb = tBase + (uint32_t)s * ESTG;
            cp16(sb + aRow0 * 160 + aQ0 * 16, Abase + (size_t)aRow0 * H_ + s * 32 + aQ0 * 4);
            cp16(sb + aRow1 * 160 + aQ1 * 16, Abase + (size_t)aRow1 * H_ + s * 32 + aQ1 * 4);
            cp16(sb + EASZ + wRow0 * 80 + wQ0 * 16, Wb2 + (size_t)wRow0 * H_ + s * 32 + wQ0 * 8);
            cp16(sb + EASZ + wRow1 * 80 + wQ1 * 16, Wb2 + (size_t)wRow1 * H_ + s * 32 + wQ1 * 8);
            CP_COMMIT();
        }

        for (int it = 0; it < 16; it++) {
            const int s = it & 3;
            CP_WAIT(2);
            __syncthreads();

            const float* sA = (const float*)(tiles + s * ESTG);
            const uint32_t wOff = tBase + (uint32_t)s * ESTG + EASZ;

#pragma unroll
            for (int ks = 0; ks < 2; ks++) {
                uint32_t af[4][4];
#pragma unroll
                for (int mi = 0; mi < 4; mi++) {
                    const int rb = wm * 64 + mi * 16 + g;
                    const int cb = ks * 16 + tg * 2;
                    float2 f0 = *(const float2*)&sA[rb * 40 + cb];
                    float2 f1 = *(const float2*)&sA[(rb + 8) * 40 + cb];
                    float2 f2 = *(const float2*)&sA[rb * 40 + cb + 8];
                    float2 f3 = *(const float2*)&sA[(rb + 8) * 40 + cb + 8];
                    af[mi][0] = packh2(f0.x, f0.y);
                    af[mi][1] = packh2(f1.x, f1.y);
                    af[mi][2] = packh2(f2.x, f2.y);
                    af[mi][3] = packh2(f3.x, f3.y);
                }
                uint32_t bt[2][4];
#pragma unroll
                for (int nt = 0; nt < 2; nt++)
                    ldsm4(bt[nt], wOff + (uint32_t)(wn * 32 + nt * 16 + lr) * 80 + ks * 32 + lb);
#pragma unroll
                for (int mi = 0; mi < 4; mi++)
#pragma unroll
                    for (int ni = 0; ni < 4; ni++) {
                        const int nt = ni >> 1, sub = ni & 1;
                        mma16816(acc[mi][ni], af[mi], bt[nt][sub ? 1 : 0], bt[nt][sub ? 3 : 2]);
                    }
            }
            if (it + 3 < 16) {
                const int ns = (it + 3) & 3;
                const uint32_t sb = tBase + (uint32_t)ns * ESTG;
                cp16(sb + aRow0 * 160 + aQ0 * 16, Abase + (size_t)aRow0 * H_ + (it + 3) * 32 + aQ0 * 4);
                cp16(sb + aRow1 * 160 + aQ1 * 16, Abase + (size_t)aRow1 * H_ + (it + 3) * 32 + aQ1 * 4);
                cp16(sb + EASZ + wRow0 * 80 + wQ0 * 16, Wb2 + (size_t)wRow0 * H_ + (it + 3) * 32 + wQ0 * 8);
                cp16(sb + EASZ + wRow1 * 80 + wQ1 * 16, Wb2 + (size_t)wRow1 * H_ + (it + 3) * 32 + wQ1 * 8);
            }
            CP_COMMIT();
        }

        // epilogue for this 256-col chunk
#pragma unroll
        for (int mi = 0; mi < 4; mi++)
#pragma unroll
            for (int hf = 0; hf < 2; hf++) {
                const int rl = wm * 64 + mi * 16 + g + hf * 8;
                const float* WhR = Wh + (size_t)(b0 + rl) * H_;
                float s = 0.f;
#pragma unroll
                for (int ni = 0; ni < 4; ni++) {
                    const int col = nc * 256 + wn * 32 + ni * 8 + tg * 2;
                    float v0 = acc[mi][ni][hf * 2 + 0] + Ub[col] + WhR[col];
                    float v1 = acc[mi][ni][hf * 2 + 1] + Ub[col + 1] + WhR[col + 1];
                    s += ftanh(v0) * aw[col] + ftanh(v1) * aw[col + 1];
                }
                s += __shfl_xor_sync(0xffffffffu, s, 1);
                s += __shfl_xor_sync(0xffffffffu, s, 2);
                if (tg == 0) atomicAdd(&esum[rl], s);
            }
        __syncthreads();   // stages re-written by next nc's prologue
    }
    if (tid < 128) {
        const int r = r0 + tid;
        energyT[(size_t)(r & (B_ - 1)) * S_ + (r >> 9)] = esum[tid] + ab[0];
    }
}

// ============================================================
// GRU fused layer (exact R14 version): 32-k chunks, 3-stage
// cp.async, 256 thr, tile 64 rows x 32 h-cols, dynamic smem.
// ============================================================
#define GSTG (320 * 80)             // 25600 per stage
#define GSMEM_DYN (3 * GSTG)        // 76800

template<int KI>
__global__ void __launch_bounds__(256, 1) gru_fused_kernel(
    const __half* __restrict__ AiH, const __half* __restrict__ WiH,
    const __half* __restrict__ AhH, const __half* __restrict__ WhH,
    const float* __restrict__ Ahf,
    const float* __restrict__ bi, const float* __restrict__ bh,
    float* __restrict__ hout, __half* __restrict__ houtH) {
    extern __shared__ __align__(16) char sm[];

    const int tid = threadIdx.x;
    const int lane = tid & 31, wid = tid >> 5;
    const int wm = wid >> 1, wn = wid & 1;
    const int gl = lane >> 2, tg = lane & 3;
    const int lr = (lane & 7) + ((lane >> 3) & 1) * 8;
    const int lb = ((lane >> 4) & 1) * 16;
    const int m0 = blockIdx.y * 64;
    const int nb = blockIdx.x * 32;
    const uint32_t base = smem_u32(sm);

    const __half* srcp[5];
    uint32_t dsto[5];
    bool ish[5];
#pragma unroll
    for (int i = 0; i < 5; i++) {
        const int idx = i * 256 + tid;
        const int row = idx >> 2, quad = idx & 3;
        const __half* p;
        bool h;
        if (row < 64)       { p = AiH + (size_t)(m0 + row) * KI; h = false; }
        else if (row < 128) { p = AhH + (size_t)(m0 + row - 64) * H_; h = true; }
        else if (row < 224) { const int q = row - 128; p = WiH + (size_t)((q >> 5) * H_ + nb + (q & 31)) * KI; h = false; }
        else                { const int q = row - 224; p = WhH + (size_t)((q >> 5) * H_ + nb + (q & 31)) * H_; h = true; }
        srcp[i] = p + quad * 8;
        dsto[i] = row * 80 + quad * 16;
        ish[i] = h;
    }

    float acc_rz[2][2][4] = {};
    float acc_n0[2][4] = {};
    float acc_n1[2][4] = {};

    constexpr int NIT = KI / 32;    // 24 (layer0) or 16
    constexpr int NHIT = H_ / 32;   // 16

#pragma unroll
    for (int s = 0; s < 2; s++) {
#pragma unroll
        for (int i = 0; i < 5; i++)
            if (!ish[i] || s < NHIT)
                cp16(base + s * GSTG + dsto[i], srcp[i] + s * 32);
        CP_COMMIT();
    }

    for (int it = 0; it < NIT; it++) {
        const int s = it % 3;
        CP_WAIT(1);
        __syncthreads();

        const uint32_t off = base + (uint32_t)s * GSTG;
        const bool act_h = (it < NHIT);
#pragma unroll
        for (int ks = 0; ks < 2; ks++) {
            const uint32_t lbk = (uint32_t)(ks * 32 + lb);
            uint32_t afi[4], afh[4], bwi[3][4], bwh[3][4];
            ldsm4(afi, off + (uint32_t)(wm * 16 + lr) * 80 + lbk);
#pragma unroll
            for (int gt = 0; gt < 3; gt++)
                ldsm4(bwi[gt], off + (uint32_t)(128 + gt * 32 + wn * 16 + lr) * 80 + lbk);
            if (act_h) {
                ldsm4(afh, off + (uint32_t)(64 + wm * 16 + lr) * 80 + lbk);
#pragma unroll
                for (int gt = 0; gt < 3; gt++)
                    ldsm4(bwh[gt], off + (uint32_t)(224 + gt * 32 + wn * 16 + lr) * 80 + lbk);
            }
#pragma unroll
            for (int sub = 0; sub < 2; sub++) {
                mma16816(acc_rz[0][sub], afi, bwi[0][sub], bwi[0][sub + 2]);
                mma16816(acc_rz[1][sub], afi, bwi[1][sub], bwi[1][sub + 2]);
                mma16816(acc_n0[sub],    afi, bwi[2][sub], bwi[2][sub + 2]);
            }
            if (act_h) {
#pragma unroll
                for (int sub = 0; sub < 2; sub++) {
                    mma16816(acc_rz[0][sub], afh, bwh[0][sub], bwh[0][sub + 2]);
                    mma16816(acc_rz[1][sub], afh, bwh[1][sub], bwh[1][sub + 2]);
                    mma16816(acc_n1[sub],    afh, bwh[2][sub], bwh[2][sub + 2]);
                }
            }
        }
        if (it + 2 < NIT) {
            const int ns = (it + 2) % 3;
#pragma unroll
            for (int i = 0; i < 5; i++)
                if (!ish[i] || (it + 2) < NHIT)
                    cp16(base + ns * GSTG + dsto[i], srcp[i] + (it + 2) * 32);
        }
        CP_COMMIT();
    }

#pragma unroll
    for (int hf = 0; hf < 2; hf++) {
        const int row = m0 + wm * 16 + gl + hf * 8;
#pragma unroll
        for (int sub = 0; sub < 2; sub++) {
            const int col = nb + wn * 16 + sub * 8 + tg * 2;
            float2 hp = *(const float2*)&Ahf[(size_t)row * H_ + col];
            float2 o;
#pragma unroll
            for (int j = 0; j < 2; j++) {
                const int cj = col + j;
                float rr = fsig(acc_rz[0][sub][hf * 2 + j] + bi[cj] + bh[cj]);
                float zz = fsig(acc_rz[1][sub][hf * 2 + j] + bi[H_ + cj] + bh[H_ + cj]);
                float nn = ftanh(acc_n0[sub][hf * 2 + j] + bi[2 * H_ + cj] +
                                 rr * (acc_n1[sub][hf * 2 + j] + bh[2 * H_ + cj]));
                float hv = j ? hp.y : hp.x;
                float res = fmaf(zz, hv - nn, nn);
                if (j) o.y = res; else o.x = res;
            }
            *(float2*)&hout[(size_t)row * H_ + col] = o;
            *(__half2*)&houtH[(size_t)row * H_ + col] = __float22half2_rn(o);
        }
    }
}

// ---------------- small GEMM: C[M,N] = A@W^T + bias (fp32 in, 64x64) ----------------
__global__ void __launch_bounds__(256, 2) sgemm64_kernel(
    const float* __restrict__ A, const float* __restrict__ W,
    const float* __restrict__ bias, float* __restrict__ C, int K, int N) {
    __shared__ __align__(16) __half sm[2 * 128 * 24];

    const int tid = threadIdx.x;
    const int lane = tid & 31, wid = tid >> 5;
    const int wm = wid >> 1, wn = wid & 1;
    const int g = lane >> 2, tg = lane & 3;
    const int lr = (lane & 7) + ((lane >> 3) & 1) * 8;
    const int lb = ((lane >> 4) & 1) * 16;
    const int m0 = blockIdx.y * 64, n0 = blockIdx.x * 64;
    const uint32_t base = smem_u32(sm);

    const int r = tid >> 2, c = (tid & 3) * 4;
    float acc[4][4] = {};
    float4 ra, rw;
    ra = *(const float4*)&A[(size_t)(m0 + r) * K + c];
    rw = *(const float4*)&W[(size_t)(n0 + r) * K + c];
    sts16(sm + r * 24 + c, ra);
    sts16(sm + (64 + r) * 24 + c, rw);
    __syncthreads();

    const int nk = K / 16;
    for (int kt = 0; kt < nk; kt++) {
        const int p = kt & 1;
        if (kt + 1 < nk) {
            ra = *(const float4*)&A[(size_t)(m0 + r) * K + (kt + 1) * 16 + c];
            rw = *(const float4*)&W[(size_t)(n0 + r) * K + (kt + 1) * 16 + c];
        }
        const uint32_t off = base + (uint32_t)p * 128 * 48;
        uint32_t af[4], bt[2][4];
        ldsm4(af, off + (uint32_t)(wm * 16 + lr) * 48 + lb);
#pragma unroll
        for (int nt = 0; nt < 2; nt++)
            ldsm4(bt[nt], off + (uint32_t)(64 + wn * 32 + nt * 16 + lr) * 48 + lb);
#pragma unroll
        for (int ni = 0; ni < 4; ni++) {
            const int nt = ni >> 1, sub = ni & 1;
            mma16816(acc[ni], af, bt[nt][sub ? 1 : 0], bt[nt][sub ? 3 : 2]);
        }
        if (kt + 1 < nk) {
            __half* d = sm + (p ^ 1) * 128 * 24;
            sts16(d + r * 24 + c, ra);
            sts16(d + (64 + r) * 24 + c, rw);
        }
        __syncthreads();
    }

#pragma unroll
    for (int hf = 0; hf < 2; hf++) {
        const int row = m0 + wm * 16 + g + hf * 8;
#pragma unroll
        for (int ni = 0; ni < 4; ni++) {
            const int col = n0 + wn * 32 + ni * 8 + tg * 2;
            float2 o;
            o.x = acc[ni][hf * 2 + 0] + bias[col];
            o.y = acc[ni][hf * 2 + 1] + bias[col + 1];
            *(float2*)&C[(size_t)row * N + col] = o;
        }
    }
}

// ============================================================
// attn+context+emb: grid (4, B), 128 threads, 8-way MLP.
// ============================================================
__global__ void __launch_bounds__(128) attn_ctx_kernel(
    const float* __restrict__ energyT, const float* __restrict__ Es,
    const int* __restrict__ x, const float* __restrict__ emb,
    __half* __restrict__ rnnH) {
    __shared__ float sv[S_];
    __shared__ float att[S_];
    const int q = blockIdx.x;
    const int b = blockIdx.y;
    const int t = threadIdx.x;

    float e0 = energyT[(size_t)b * S_ + t];
    float e1 = energyT[(size_t)b * S_ + 128 + t];
    sv[t] = fmaxf(e0, e1);
    __syncthreads();
    for (int off = 64; off; off >>= 1) {
        if (t < off) sv[t] = fmaxf(sv[t], sv[t + off]);
        __syncthreads();
    }
    const float m = sv[0];
    __syncthreads();
    float x0 = __expf(e0 - m), x1 = __expf(e1 - m);
    att[t] = x0;
    att[t + 128] = x1;
    sv[t] = x0 + x1;
    __syncthreads();
    for (int off = 64; off; off >>= 1) {
        if (t < off) sv[t] += sv[t + off];
        __syncthreads();
    }
    const float inv = __fdividef(1.f, sv[0]);
    __syncthreads();

    // context: h = q*128 + t, 8 independent accumulators
    const int h = q * 128 + t;
    const float* base = Es + (size_t)b * H_ + h;
    float a0 = 0.f, a1 = 0.f, a2 = 0.f, a3 = 0.f;
    float a4 = 0.f, a5 = 0.f, a6 = 0.f, a7 = 0.f;
    for (int s = 0; s < S_; s += 8) {
        a0 = fmaf(att[s + 0], base[(size_t)(s + 0) * B_ * H_], a0);
        a1 = fmaf(att[s + 1], base[(size_t)(s + 1) * B_ * H_], a1);
        a2 = fmaf(att[s + 2], base[(size_t)(s + 2) * B_ * H_], a2);
        a3 = fmaf(att[s + 3], base[(size_t)(s + 3) * B_ * H_], a3);
        a4 = fmaf(att[s + 4], base[(size_t)(s + 4) * B_ * H_], a4);
        a5 = fmaf(att[s + 5], base[(size_t)(s + 5) * B_ * H_], a5);
        a6 = fmaf(att[s + 6], base[(size_t)(s + 6) * B_ * H_], a6);
        a7 = fmaf(att[s + 7], base[(size_t)(s + 7) * B_ * H_], a7);
    }
    float ctx = ((a0 + a1) + (a2 + a3)) + ((a4 + a5) + (a6 + a7));
    rnnH[(size_t)b * (H_ + E_) + h] = __float2half(ctx * inv);

    // embedding: 4 blocks x 64 lanes cover E_=256
    if (t < 64) {
        const int col = q * 64 + t;
        rnnH[(size_t)b * (H_ + E_) + H_ + col] = __float2half(emb[(size_t)x[b] * E_ + col]);
    }
}

// ---------------- launch ----------------
extern "C" void kernel_launch(void* const* d_in, const int* in_sizes, int n_in,
                              void* d_out, int out_size) {
    const int*   x      = (const int*)  d_in[0];
    const float* Es     = (const float*)d_in[1];
    const float* hidden = (const float*)d_in[2];
    const float* emb    = (const float*)d_in[4];
    const float* Uw     = (const float*)d_in[5];
    const float* Ub     = (const float*)d_in[6];
    const float* Ww     = (const float*)d_in[7];
    const float* Wb     = (const float*)d_in[8];
    const float* aw     = (const float*)d_in[9];
    const float* ab     = (const float*)d_in[10];
    const float* w_ih0  = (const float*)d_in[11];
    const float* w_hh0  = (const float*)d_in[12];
    const float* b_ih0  = (const float*)d_in[13];
    const float* b_hh0  = (const float*)d_in[14];
    const float* w_ih_r = (const float*)d_in[15];
    const float* w_hh_r = (const float*)d_in[16];
    const float* b_ih_r = (const float*)d_in[17];
    const float* b_hh_r = (const float*)d_in[18];
    const float* fcw    = (const float*)d_in[19];
    const float* fcb    = (const float*)d_in[20];

    float* out     = (float*)d_out;
    float* pred    = out;               // [B, OUT]
    float* hid_out = out + B_ * OUT_;   // [L, B, H]

    float *Wh, *energyT;
    __half *UwH, *WiH0, *WhH0, *WiHr, *WhHr, *hidH, *rnnH, *houtH;
    cudaGetSymbolAddress((void**)&Wh,      g_Wh);
    cudaGetSymbolAddress((void**)&energyT, g_energyT);
    cudaGetSymbolAddress((void**)&UwH,     g_UwH);
    cudaGetSymbolAddress((void**)&WiH0,    g_WiH0);
    cudaGetSymbolAddress((void**)&WhH0,    g_WhH0);
    cudaGetSymbolAddress((void**)&WiHr,    g_WiHr);
    cudaGetSymbolAddress((void**)&WhHr,    g_WhHr);
    cudaGetSymbolAddress((void**)&hidH,    g_hidH);
    cudaGetSymbolAddress((void**)&rnnH,    g_rnnH);
    cudaGetSymbolAddress((void**)&houtH,   g_houtH);

    cudaFuncSetAttribute(energy_async_kernel,
                         cudaFuncAttributeMaxDynamicSharedMemorySize, ESMEM_DYN);
    cudaFuncSetAttribute(gru_fused_kernel<768>,
                         cudaFuncAttributeMaxDynamicSharedMemorySize, GSMEM_DYN);
    cudaFuncSetAttribute(gru_fused_kernel<512>,
                         cudaFuncAttributeMaxDynamicSharedMemorySize, GSMEM_DYN);

    const float* hlast = hidden + (size_t)(L_ - 1) * B_ * H_;

    // 0) all fp32 -> fp16 conversions in one launch
    cvt_all_kernel<<<CVT_BLOCKS, 256>>>(Uw, UwH, w_ih0, WiH0, w_hh0, WhH0,
                                        w_ih_r, WiHr, w_hh_r, WhHr, hidden, hidH);

    // 1) Wh = hidden[-1] @ Ww^T + Wb
    sgemm64_kernel<<<dim3(H_ / 64, B_ / 64), 256>>>(hlast, Ww, Wb, Wh, H_, H_);

    // 2) fused energy -> energyT[b][s] (4-stage pipeline)
    energy_async_kernel<<<(S_ * B_) / 128, 512, ESMEM_DYN>>>(
        Es, UwH, Ub, Wh, aw, ab, energyT);

    // 3) softmax + context + embedding -> fp16 rnn
    attn_ctx_kernel<<<dim3(4, B_), 128>>>(energyT, Es, x, emb, rnnH);

    // 4) fused GRU layers (4 launches — faster than software grid barrier)
    gru_fused_kernel<768><<<dim3(H_ / 32, B_ / 64), 256, GSMEM_DYN>>>(
        rnnH, WiH0, hidH, WhH0, hidden, b_ih0, b_hh0, hid_out, houtH);
    for (int l = 1; l < L_; l++) {
        gru_fused_kernel<512><<<dim3(H_ / 32, B_ / 64), 256, GSMEM_DYN>>>(
            houtH + (size_t)(l - 1) * B_ * H_,
            WiHr + (size_t)(l - 1) * 3 * H_ * H_,
            hidH + (size_t)l * B_ * H_,
            WhHr + (size_t)(l - 1) * 3 * H_ * H_,
            hidden + (size_t)l * B_ * H_,
            b_ih_r + (size_t)(l - 1) * 3 * H_,
            b_hh_r + (size_t)(l - 1) * 3 * H_,
            hid_out + (size_t)l * B_ * H_,
            houtH + (size_t)l * B_ * H_);
    }

    // 5) predictions = h_last @ fcw^T + fcb
    sgemm64_kernel<<<dim3(OUT_ / 64, B_ / 64), 256>>>(
        hid_out + (size_t)(L_ - 1) * B_ * H_, fcw, fcb, pred, H_, OUT_);
}